// round 7
// baseline (speedup 1.0000x reference)
#include <cuda_runtime.h>
#include <cuda_bf16.h>
#include <cstdint>

#define B_   32
#define CIN  256
#define COUT 256
#define H_   56
#define W_   56
#define PX   (H_ * W_)        // 3136
#define NTILE 128             // px per CTA
#define NTILES 25             // ceil(3136/128)

// ---------- static scratch ----------
__device__ __align__(16) __nv_bfloat16 g_xhi[(size_t)B_ * PX * CIN];  // NHWC hi
__device__ __align__(16) __nv_bfloat16 g_xlo[(size_t)B_ * PX * CIN];  // NHWC lo
// A tiles: [tap][chunk][row 0..255][64 ic] bf16, rows 128B, XOR-pre-swizzled (32KB each)
__device__ __align__(16) __nv_bfloat16 g_A[9 * 4 * 256 * 64];
__device__ float g_scale[COUT];   // inv/15
__device__ float g_bias[COUT];
__device__ unsigned g_maxbits;

// ---------- helpers ----------
__device__ __forceinline__ uint32_t smem_u32(const void* p) {
    uint32_t a;
    asm("{ .reg .u64 t; cvta.to.shared.u64 t, %1; cvt.u32.u64 %0, t; }" : "=r"(a) : "l"(p));
    return a;
}
__device__ __forceinline__ void cp16(uint32_t s, const void* g, uint32_t bytes) {
    asm volatile("cp.async.ca.shared.global [%0], [%1], 16, %2;"
                 :: "r"(s), "l"(g), "r"(bytes) : "memory");
}
#define CP_COMMIT() asm volatile("cp.async.commit_group;" ::: "memory")
#define CP_WAIT(n)  asm volatile("cp.async.wait_group %0;" :: "n"(n) : "memory")

__device__ __forceinline__ void ldsm4(uint32_t& r0, uint32_t& r1, uint32_t& r2, uint32_t& r3, uint32_t a) {
    asm volatile("ldmatrix.sync.aligned.m8n8.x4.shared.b16 {%0,%1,%2,%3}, [%4];"
                 : "=r"(r0), "=r"(r1), "=r"(r2), "=r"(r3) : "r"(a));
}
__device__ __forceinline__ void mma16816(float* c, const uint32_t* a, uint32_t b0, uint32_t b1) {
    asm volatile("mma.sync.aligned.m16n8k16.row.col.f32.bf16.bf16.f32 "
                 "{%0,%1,%2,%3}, {%4,%5,%6,%7}, {%8,%9}, {%0,%1,%2,%3};"
                 : "+f"(c[0]), "+f"(c[1]), "+f"(c[2]), "+f"(c[3])
                 : "r"(a[0]), "r"(a[1]), "r"(a[2]), "r"(a[3]), "r"(b0), "r"(b1));
}

// ---------- prep kernels ----------
__global__ void k_init() { if (threadIdx.x == 0) g_maxbits = 0u; }

__global__ void k_maxred(const float* __restrict__ w, int n) {
    __shared__ float s[256];
    float m = 0.f;
    for (int i = blockIdx.x * blockDim.x + threadIdx.x; i < n; i += gridDim.x * blockDim.x)
        m = fmaxf(m, fabsf(w[i]));
    s[threadIdx.x] = m;
    __syncthreads();
    for (int o = 128; o > 0; o >>= 1) {
        if (threadIdx.x < o) s[threadIdx.x] = fmaxf(s[threadIdx.x], s[threadIdx.x + o]);
        __syncthreads();
    }
    if (threadIdx.x == 0) atomicMax(&g_maxbits, __float_as_uint(s[0]));
}

__global__ void k_bn(const float* __restrict__ gamma, const float* __restrict__ beta,
                     const float* __restrict__ mean, const float* __restrict__ var) {
    int i = threadIdx.x;
    if (i < COUT) {
        float inv = gamma[i] / sqrtf(var[i] + 1e-5f);
        g_scale[i] = inv * (1.f / 15.f);
        g_bias[i]  = beta[i] - mean[i] * inv;
    }
}

// weights -> integer m = 2k-15 (exact in bf16), PRE-swizzled A tiles (M=256 rows)
__global__ void k_prepw(const float* __restrict__ w) {
    int idx = blockIdx.x * blockDim.x + threadIdx.x;
    if (idx >= COUT * CIN * 9) return;
    float T = tanhf(__uint_as_float(g_maxbits));
    int oc  = idx / (CIN * 9);
    int rem = idx - oc * (CIN * 9);
    int ic  = rem / 9;
    int tap = rem - ic * 9;
    float t = tanhf(w[idx]);
    float k = rintf((t / (2.f * T) + 0.5f) * 15.f);   // 0..15
    float m = 2.f * k - 15.f;                          // odd int, |m|<=15
    int chunk = ic >> 6, icc = ic & 63;
    int tile = tap * 4 + chunk;
    // swizzle within 128B row: 16B-unit q ^= (oc & 7)
    int lowsw = (icc * 2) ^ ((oc & 7) << 4);
    g_A[tile * 16384 + ((oc * 128 + lowsw) >> 1)] = __float2bfloat16(m);
}

// NCHW fp32 -> NHWC bf16 hi + lo
__global__ void k_prepx(const float* __restrict__ x) {
    __shared__ float s[64][57];
    int y = blockIdx.x, b = blockIdx.y;
    int tid = threadIdx.x;
    for (int ch = 0; ch < 4; ++ch) {
        for (int i = tid; i < 64 * 56; i += 256) {
            int ic = i / 56, xx = i - ic * 56;
            s[ic][xx] = x[(((size_t)b * CIN + ch * 64 + ic) * H_ + y) * W_ + xx];
        }
        __syncthreads();
        for (int i = tid; i < 56 * 64; i += 256) {
            int xx = i >> 6, ic = i & 63;
            float v = s[ic][xx];
            __nv_bfloat16 hi = __float2bfloat16(v);
            __nv_bfloat16 lo = __float2bfloat16(v - __bfloat162float(hi));
            size_t dst = (((size_t)b * H_ + y) * W_ + xx) * CIN + ch * 64 + ic;
            g_xhi[dst] = hi;
            g_xlo[dst] = lo;
        }
        __syncthreads();
    }
}

// ---------- conv: HMMA implicit GEMM, M=256 x N=128 per CTA ----------
// smem: A0 @0 (32K), A1 @32K, B0 @64K (16K), B1 @80K; total 96K
#define SA0 0
#define SA1 32768
#define SB0 65536
#define SB1 81920
#define SM_TOT 98304

__global__ __launch_bounds__(256, 1)
void k_conv(const float* __restrict__ alpha, float* __restrict__ out) {
    extern __shared__ char smem[];
    const uint32_t sb = smem_u32(smem);
    const int tid = threadIdx.x, wid = tid >> 5, lane = tid & 31;
    const int tile = blockIdx.x;           // n tile (0..24)
    const int b    = blockIdx.y;
    const int wm = wid >> 1;               // 0..3 -> m offset 64*wm
    const int wn = wid & 1;                // 0..1 -> n offset 64*wn

    const uint32_t aoff[2] = {SA0, SA1};
    const uint32_t boff[2] = {SB0, SB1};

    auto prefetch = [&](int s) {
        const int pair = s >> 1, split = s & 1;
        const int tap = pair >> 2, chunk = pair & 3;
        if (split == 0) {  // stage A: 32KB LINEAR copy (g_A is pre-swizzled!)
            const char* Asrc = (const char*)g_A + (size_t)(tap * 4 + chunk) * 32768;
            uint32_t Ad = sb + aoff[pair & 1];
            #pragma unroll
            for (int j = 0; j < 8; ++j) {
                int idx = tid + j * 256;
                cp16(Ad + idx * 16, Asrc + idx * 16, 16);
            }
        }
        {   // stage B: 128 px rows x 128B (64 ic), swizzle on store, zfill OOB/halo
            const __nv_bfloat16* xs = split ? g_xlo : g_xhi;
            const int dy = tap / 3 - 1, dx = tap % 3 - 1;
            uint32_t Bd = sb + boff[s & 1];
            #pragma unroll
            for (int j = 0; j < 4; ++j) {
                int idx = tid + j * 256;
                int row = idx >> 3, q = idx & 7;
                int px = tile * NTILE + row;
                int y = px / 56, xx = px - y * 56;
                int gy = y + dy, gx = xx + dx;
                bool ok = (px < PX) && ((unsigned)gy < (unsigned)H_) && ((unsigned)gx < (unsigned)W_);
                const __nv_bfloat16* src = ok
                    ? xs + ((((size_t)b * H_ + gy) * W_ + gx) * CIN + chunk * 64 + q * 8)
                    : xs;
                cp16(Bd + row * 128 + ((q ^ (row & 7)) * 16), src, ok ? 16u : 0u);
            }
        }
        CP_COMMIT();
    };

    float acc[4][8][4];
    #pragma unroll
    for (int i = 0; i < 4; ++i)
        #pragma unroll
        for (int jj = 0; jj < 8; ++jj)
            #pragma unroll
            for (int kq = 0; kq < 4; ++kq) acc[i][jj][kq] = 0.f;

    prefetch(0);

    const int lrow = lane & 15;
    const int lkh  = lane >> 4;

    for (int s = 0; s < 72; ++s) {
        if (s + 1 < 72) { prefetch(s + 1); CP_WAIT(1); }
        else            { CP_WAIT(0); }
        __syncthreads();

        const uint32_t Ab = sb + aoff[(s >> 1) & 1];
        const uint32_t Bb = sb + boff[s & 1];

        #pragma unroll
        for (int ks = 0; ks < 4; ++ks) {
            const int qbase = ks * 2 + lkh;
            uint32_t a[4][4];
            #pragma unroll
            for (int mt = 0; mt < 4; ++mt) {
                int r = wm * 64 + mt * 16 + lrow;
                ldsm4(a[mt][0], a[mt][1], a[mt][2], a[mt][3],
                      Ab + r * 128 + ((qbase ^ (r & 7)) * 16));
            }
            uint32_t br[4][4];
            #pragma unroll
            for (int bt = 0; bt < 4; ++bt) {
                int r = wn * 64 + bt * 16 + lrow;
                ldsm4(br[bt][0], br[bt][1], br[bt][2], br[bt][3],
                      Bb + r * 128 + ((qbase ^ (r & 7)) * 16));
            }
            #pragma unroll
            for (int mt = 0; mt < 4; ++mt) {
                #pragma unroll
                for (int bt = 0; bt < 4; ++bt) {
                    mma16816(acc[mt][bt * 2 + 0], a[mt], br[bt][0], br[bt][2]);
                    mma16816(acc[mt][bt * 2 + 1], a[mt], br[bt][1], br[bt][3]);
                }
            }
        }
        __syncthreads();
    }

    // ---------- epilogue: BN + PACT, direct fp32 stores ----------
    const float av = alpha[0];
    const float istep = 15.f / av, step = av / 15.f;
    #pragma unroll
    for (int mt = 0; mt < 4; ++mt) {
        const int r0 = wm * 64 + mt * 16 + (lane >> 2);
        #pragma unroll
        for (int half = 0; half < 2; ++half) {
            const int oc = r0 + half * 8;
            const float sc = g_scale[oc], bi = g_bias[oc];
            float* ob = out + ((size_t)b * COUT + oc) * PX;
            #pragma unroll
            for (int nt = 0; nt < 8; ++nt) {
                const int px = tile * NTILE + wn * 64 + nt * 8 + (lane & 3) * 2;
                if (px + 1 < PX) {
                    float y0 = acc[mt][nt][half * 2 + 0] * sc + bi;
                    float y1 = acc[mt][nt][half * 2 + 1] * sc + bi;
                    y0 = fminf(fmaxf(y0, 0.f), av);
                    y1 = fminf(fmaxf(y1, 0.f), av);
                    float2 v = make_float2(rintf(y0 * istep) * step, rintf(y1 * istep) * step);
                    *(float2*)(ob + px) = v;
                } else if (px < PX) {
                    float y0 = acc[mt][nt][half * 2 + 0] * sc + bi;
                    y0 = fminf(fmaxf(y0, 0.f), av);
                    ob[px] = rintf(y0 * istep) * step;
                }
            }
        }
    }
}

extern "C" void kernel_launch(void* const* d_in, const int* in_sizes, int n_in,
                              void* d_out, int out_size) {
    const float* x      = (const float*)d_in[0];
    const float* weight = (const float*)d_in[1];
    const float* gamma  = (const float*)d_in[2];
    const float* beta   = (const float*)d_in[3];
    const float* mean   = (const float*)d_in[4];
    const float* var    = (const float*)d_in[5];
    const float* alpha  = (const float*)d_in[6];
    float* out = (float*)d_out;

    k_init<<<1, 32>>>();
    k_bn<<<1, 256>>>(gamma, beta, mean, var);
    k_maxred<<<576, 256>>>(weight, COUT * CIN * 9);
    k_prepw<<<(COUT * CIN * 9 + 255) / 256, 256>>>(weight);
    k_prepx<<<dim3(H_, B_), 256>>>(x);

    cudaFuncSetAttribute(k_conv, cudaFuncAttributeMaxDynamicSharedMemorySize, SM_TOT);
    k_conv<<<dim3(NTILES, B_), 256, SM_TOT>>>(alpha, out);
    (void)in_sizes; (void)n_in; (void)out_size;
}

// round 10
// speedup vs baseline: 1.0105x; 1.0105x over previous
#include <cuda_runtime.h>
#include <cuda_bf16.h>
#include <cstdint>

#define B_   32
#define CIN  256
#define COUT 256
#define H_   56
#define W_   56
#define PX   (H_ * W_)        // 3136
#define NTILE 128             // px per CTA
#define NTILES 25             // ceil(3136/128)

// ---------- static scratch ----------
__device__ __align__(16) __nv_bfloat16 g_xhi[(size_t)B_ * PX * CIN];  // NHWC hi
__device__ __align__(16) __nv_bfloat16 g_xlo[(size_t)B_ * PX * CIN];  // NHWC lo
// A tiles: [tap][chunk][mhalf][row 0..127][64 ic] bf16, rows 128B, pre-swizzled, 16KB each
__device__ __align__(16) __nv_bfloat16 g_A[9 * 4 * 2 * 128 * 64];
__device__ float g_scale[COUT];   // inv/15
__device__ float g_bias[COUT];
__device__ unsigned g_maxbits;

// ---------- helpers ----------
__device__ __forceinline__ uint32_t smem_u32(const void* p) {
    uint32_t a;
    asm("{ .reg .u64 t; cvta.to.shared.u64 t, %1; cvt.u32.u64 %0, t; }" : "=r"(a) : "l"(p));
    return a;
}
__device__ __forceinline__ void cp16(uint32_t s, const void* g, uint32_t bytes) {
    asm volatile("cp.async.ca.shared.global [%0], [%1], 16, %2;"
                 :: "r"(s), "l"(g), "r"(bytes) : "memory");
}
#define CP_COMMIT() asm volatile("cp.async.commit_group;" ::: "memory")
#define CP_WAIT(n)  asm volatile("cp.async.wait_group %0;" :: "n"(n) : "memory")

__device__ __forceinline__ void ldsm4(uint32_t& r0, uint32_t& r1, uint32_t& r2, uint32_t& r3, uint32_t a) {
    asm volatile("ldmatrix.sync.aligned.m8n8.x4.shared.b16 {%0,%1,%2,%3}, [%4];"
                 : "=r"(r0), "=r"(r1), "=r"(r2), "=r"(r3) : "r"(a));
}
__device__ __forceinline__ void mma16816(float* c, const uint32_t* a, uint32_t b0, uint32_t b1) {
    asm volatile("mma.sync.aligned.m16n8k16.row.col.f32.bf16.bf16.f32 "
                 "{%0,%1,%2,%3}, {%4,%5,%6,%7}, {%8,%9}, {%0,%1,%2,%3};"
                 : "+f"(c[0]), "+f"(c[1]), "+f"(c[2]), "+f"(c[3])
                 : "r"(a[0]), "r"(a[1]), "r"(a[2]), "r"(a[3]), "r"(b0), "r"(b1));
}

// ---------- prep kernels ----------
__global__ void k_init() { if (threadIdx.x == 0) g_maxbits = 0u; }

__global__ void k_maxred(const float* __restrict__ w, int n) {
    __shared__ float s[256];
    float m = 0.f;
    for (int i = blockIdx.x * blockDim.x + threadIdx.x; i < n; i += gridDim.x * blockDim.x)
        m = fmaxf(m, fabsf(w[i]));
    s[threadIdx.x] = m;
    __syncthreads();
    for (int o = 128; o > 0; o >>= 1) {
        if (threadIdx.x < o) s[threadIdx.x] = fmaxf(s[threadIdx.x], s[threadIdx.x + o]);
        __syncthreads();
    }
    if (threadIdx.x == 0) atomicMax(&g_maxbits, __float_as_uint(s[0]));
}

__global__ void k_bn(const float* __restrict__ gamma, const float* __restrict__ beta,
                     const float* __restrict__ mean, const float* __restrict__ var) {
    int i = threadIdx.x;
    if (i < COUT) {
        float inv = gamma[i] / sqrtf(var[i] + 1e-5f);
        g_scale[i] = inv * (1.f / 15.f);
        g_bias[i]  = beta[i] - mean[i] * inv;
    }
}

// weights -> integer m = 2k-15 (exact in bf16), pre-swizzled 16KB A tiles (R5 layout)
__global__ void k_prepw(const float* __restrict__ w) {
    int idx = blockIdx.x * blockDim.x + threadIdx.x;
    if (idx >= COUT * CIN * 9) return;
    float T = tanhf(__uint_as_float(g_maxbits));
    int oc  = idx / (CIN * 9);
    int rem = idx - oc * (CIN * 9);
    int ic  = rem / 9;
    int tap = rem - ic * 9;
    float t = tanhf(w[idx]);
    float k = rintf((t / (2.f * T) + 0.5f) * 15.f);   // 0..15
    float m = 2.f * k - 15.f;                          // odd int, |m|<=15
    int chunk = ic >> 6, icc = ic & 63;
    int mh = oc >> 7, row = oc & 127;
    int tile = (tap * 4 + chunk) * 2 + mh;
    int byte = row * 128 + icc * 2;
    int sw = byte ^ ((byte >> 3) & 0x70);              // within-row unit swizzle
    g_A[tile * 8192 + (sw >> 1)] = __float2bfloat16(m);
}

// NCHW fp32 -> NHWC bf16 hi + lo
__global__ void k_prepx(const float* __restrict__ x) {
    __shared__ float s[64][57];
    int y = blockIdx.x, b = blockIdx.y;
    int tid = threadIdx.x;
    for (int ch = 0; ch < 4; ++ch) {
        for (int i = tid; i < 64 * 56; i += 256) {
            int ic = i / 56, xx = i - ic * 56;
            s[ic][xx] = x[(((size_t)b * CIN + ch * 64 + ic) * H_ + y) * W_ + xx];
        }
        __syncthreads();
        for (int i = tid; i < 56 * 64; i += 256) {
            int xx = i >> 6, ic = i & 63;
            float v = s[ic][xx];
            __nv_bfloat16 hi = __float2bfloat16(v);
            __nv_bfloat16 lo = __float2bfloat16(v - __bfloat162float(hi));
            size_t dst = (((size_t)b * H_ + y) * W_ + xx) * CIN + ch * 64 + ic;
            g_xhi[dst] = hi;
            g_xlo[dst] = lo;
        }
        __syncthreads();
    }
}

// ---------- conv: HMMA implicit GEMM, M=128 x N=128, K=128 merged hi|lo stages ----------
// smem: A0 @0 (16K), A1 @16K, B0 @32K (32K: 128 rows x 256B), B1 @64K; total 96K
#define SA0 0
#define SA1 16384
#define SB0 32768
#define SB1 65536
#define SM_TOT 98304

__global__ __launch_bounds__(256, 2)
void k_conv(const float* __restrict__ alpha, float* __restrict__ out) {
    extern __shared__ char smem[];
    const uint32_t sb = smem_u32(smem);
    const int tid = threadIdx.x, wid = tid >> 5, lane = tid & 31;
    const int tile = blockIdx.x;           // n tile (0..24)
    const int mh   = blockIdx.y;           // 0..1
    const int b    = blockIdx.z;
    const int wm = wid >> 2;               // 0..1 -> m offset 64*wm
    const int wn = wid & 3;                // 0..3 -> n offset 32*wn

    const uint32_t aoff[2] = {SA0, SA1};
    const uint32_t boff[2] = {SB0, SB1};

    // 36 stages: tap = s>>2, chunk = s&3. B rows are 256B: [hi 128B | lo 128B].
    auto prefetch = [&](int s) {
        const int tap = s >> 2, chunk = s & 3;
        {   // stage A: 16KB linear copy (pre-swizzled in gmem)
            const char* Asrc = (const char*)g_A + (size_t)((tap * 4 + chunk) * 2 + mh) * 16384;
            uint32_t Ad = sb + aoff[s & 1];
            #pragma unroll
            for (int j = 0; j < 4; ++j) {
                int idx = tid + j * 256;
                cp16(Ad + idx * 16, Asrc + idx * 16, 16);
            }
        }
        {   // stage B: 128 px rows x 256B (64 ic hi | 64 ic lo), zfill OOB/halo
            const int dy = tap / 3 - 1, dx = tap % 3 - 1;
            uint32_t Bd = sb + boff[s & 1];
            #pragma unroll
            for (int j = 0; j < 8; ++j) {
                int idx = tid + j * 256;          // 0..2047 16B units
                int row = idx >> 4;               // px row 0..127
                int u   = idx & 15;
                int half = u >> 3, q = u & 7;
                int px = tile * NTILE + row;
                int y = px / 56, xx = px - y * 56;
                int gy = y + dy, gx = xx + dx;
                bool ok = (px < PX) && ((unsigned)gy < (unsigned)H_) && ((unsigned)gx < (unsigned)W_);
                const __nv_bfloat16* xs = half ? g_xlo : g_xhi;
                const __nv_bfloat16* src = ok
                    ? xs + ((((size_t)b * H_ + gy) * W_ + gx) * CIN + chunk * 64 + q * 8)
                    : xs;
                cp16(Bd + row * 256 + half * 128 + ((q ^ (row & 7)) * 16), src, ok ? 16u : 0u);
            }
        }
        CP_COMMIT();
    };

    float acc[4][4][4];
    #pragma unroll
    for (int i = 0; i < 4; ++i)
        #pragma unroll
        for (int jj = 0; jj < 4; ++jj)
            #pragma unroll
            for (int kq = 0; kq < 4; ++kq) acc[i][jj][kq] = 0.f;

    prefetch(0);

    const int lrow = lane & 15;
    const int lkh  = lane >> 4;

    for (int s = 0; s < 36; ++s) {
        if (s + 1 < 36) { prefetch(s + 1); CP_WAIT(1); }
        else            { CP_WAIT(0); }
        __syncthreads();

        const uint32_t Ab = sb + aoff[s & 1];
        const uint32_t Bb = sb + boff[s & 1];

        #pragma unroll
        for (int ks = 0; ks < 4; ++ks) {
            const int qbase = ks * 2 + lkh;
            // A fragments: loaded once, reused for hi and lo halves
            uint32_t a[4][4];
            #pragma unroll
            for (int mt = 0; mt < 4; ++mt) {
                int r = wm * 64 + mt * 16 + lrow;
                ldsm4(a[mt][0], a[mt][1], a[mt][2], a[mt][3],
                      Ab + r * 128 + ((qbase ^ (r & 7)) * 16));
            }
            #pragma unroll
            for (int half = 0; half < 2; ++half) {
                uint32_t br[2][4];
                #pragma unroll
                for (int bt = 0; bt < 2; ++bt) {
                    int r = wn * 32 + bt * 16 + lrow;
                    ldsm4(br[bt][0], br[bt][1], br[bt][2], br[bt][3],
                          Bb + r * 256 + half * 128 + ((qbase ^ (r & 7)) * 16));
                }
                #pragma unroll
                for (int mt = 0; mt < 4; ++mt) {
                    #pragma unroll
                    for (int bt = 0; bt < 2; ++bt) {
                        mma16816(acc[mt][bt * 2 + 0], a[mt], br[bt][0], br[bt][2]);
                        mma16816(acc[mt][bt * 2 + 1], a[mt], br[bt][1], br[bt][3]);
                    }
                }
            }
        }
        __syncthreads();
    }

    // ---------- epilogue: BN + PACT, direct fp32 stores ----------
    const float av = alpha[0];
    const float istep = 15.f / av, step = av / 15.f;
    #pragma unroll
    for (int mt = 0; mt < 4; ++mt) {
        const int r0 = wm * 64 + mt * 16 + (lane >> 2);
        #pragma unroll
        for (int half = 0; half < 2; ++half) {
            const int oc = mh * 128 + r0 + half * 8;
            const float sc = g_scale[oc], bi = g_bias[oc];
            float* ob = out + ((size_t)b * COUT + oc) * PX;
            #pragma unroll
            for (int nt = 0; nt < 4; ++nt) {
                const int px = tile * NTILE + wn * 32 + nt * 8 + (lane & 3) * 2;
                if (px + 1 < PX) {
                    float y0 = acc[mt][nt][half * 2 + 0] * sc + bi;
                    float y1 = acc[mt][nt][half * 2 + 1] * sc + bi;
                    y0 = fminf(fmaxf(y0, 0.f), av);
                    y1 = fminf(fmaxf(y1, 0.f), av);
                    float2 v = make_float2(rintf(y0 * istep) * step, rintf(y1 * istep) * step);
                    *(float2*)(ob + px) = v;
                } else if (px < PX) {
                    float y0 = acc[mt][nt][half * 2 + 0] * sc + bi;
                    y0 = fminf(fmaxf(y0, 0.f), av);
                    ob[px] = rintf(y0 * istep) * step;
                }
            }
        }
    }
}

extern "C" void kernel_launch(void* const* d_in, const int* in_sizes, int n_in,
                              void* d_out, int out_size) {
    const float* x      = (const float*)d_in[0];
    const float* weight = (const float*)d_in[1];
    const float* gamma  = (const float*)d_in[2];
    const float* beta   = (const float*)d_in[3];
    const float* mean   = (const float*)d_in[4];
    const float* var    = (const float*)d_in[5];
    const float* alpha  = (const float*)d_in[6];
    float* out = (float*)d_out;

    k_init<<<1, 32>>>();
    k_bn<<<1, 256>>>(gamma, beta, mean, var);
    k_maxred<<<576, 256>>>(weight, COUT * CIN * 9);
    k_prepw<<<(COUT * CIN * 9 + 255) / 256, 256>>>(weight);
    k_prepx<<<dim3(H_, B_), 256>>>(x);

    cudaFuncSetAttribute(k_conv, cudaFuncAttributeMaxDynamicSharedMemorySize, SM_TOT);
    k_conv<<<dim3(NTILES, 2, B_), 256, SM_TOT>>>(alpha, out);
    (void)in_sizes; (void)n_in; (void)out_size;
}

// round 12
// speedup vs baseline: 1.0677x; 1.0565x over previous
#include <cuda_runtime.h>
#include <cuda_bf16.h>
#include <cstdint>

#define B_   32
#define CIN  256
#define COUT 256
#define H_   56
#define W_   56
#define PX   (H_ * W_)        // 3136
#define NTILE 128             // px per CTA
#define NTILES 25             // ceil(3136/128)

// ---------- static scratch ----------
__device__ __align__(16) __nv_bfloat16 g_xhi[(size_t)B_ * PX * CIN];  // NHWC hi
__device__ __align__(16) __nv_bfloat16 g_xlo[(size_t)B_ * PX * CIN];  // NHWC lo
// A tiles: [tap][chunk][mhalf][row 0..127][64 ic] bf16, rows 128B, pre-swizzled, 16KB each
__device__ __align__(16) __nv_bfloat16 g_A[9 * 4 * 2 * 128 * 64];
__device__ float g_scale[COUT];   // inv/15
__device__ float g_bias[COUT];
__device__ unsigned g_maxbits;

// ---------- helpers ----------
__device__ __forceinline__ uint32_t smem_u32(const void* p) {
    uint32_t a;
    asm("{ .reg .u64 t; cvta.to.shared.u64 t, %1; cvt.u32.u64 %0, t; }" : "=r"(a) : "l"(p));
    return a;
}
__device__ __forceinline__ void cp16ca(uint32_t s, const void* g, uint32_t bytes) {
    asm volatile("cp.async.ca.shared.global [%0], [%1], 16, %2;"
                 :: "r"(s), "l"(g), "r"(bytes) : "memory");
}
__device__ __forceinline__ void cp16cg(uint32_t s, const void* g) {
    asm volatile("cp.async.cg.shared.global [%0], [%1], 16;"
                 :: "r"(s), "l"(g) : "memory");
}
#define CP_COMMIT() asm volatile("cp.async.commit_group;" ::: "memory")
#define CP_WAIT(n)  asm volatile("cp.async.wait_group %0;" :: "n"(n) : "memory")

__device__ __forceinline__ void ldsm4(uint32_t& r0, uint32_t& r1, uint32_t& r2, uint32_t& r3, uint32_t a) {
    asm volatile("ldmatrix.sync.aligned.m8n8.x4.shared.b16 {%0,%1,%2,%3}, [%4];"
                 : "=r"(r0), "=r"(r1), "=r"(r2), "=r"(r3) : "r"(a));
}
__device__ __forceinline__ void mma16816(float* c, const uint32_t* a, uint32_t b0, uint32_t b1) {
    asm volatile("mma.sync.aligned.m16n8k16.row.col.f32.bf16.bf16.f32 "
                 "{%0,%1,%2,%3}, {%4,%5,%6,%7}, {%8,%9}, {%0,%1,%2,%3};"
                 : "+f"(c[0]), "+f"(c[1]), "+f"(c[2]), "+f"(c[3])
                 : "r"(a[0]), "r"(a[1]), "r"(a[2]), "r"(a[3]), "r"(b0), "r"(b1));
}

// ---------- prep kernels ----------
__global__ void k_init() { if (threadIdx.x == 0) g_maxbits = 0u; }

__global__ void k_maxred(const float* __restrict__ w, int n) {
    __shared__ float s[256];
    float m = 0.f;
    for (int i = blockIdx.x * blockDim.x + threadIdx.x; i < n; i += gridDim.x * blockDim.x)
        m = fmaxf(m, fabsf(w[i]));
    s[threadIdx.x] = m;
    __syncthreads();
    for (int o = 128; o > 0; o >>= 1) {
        if (threadIdx.x < o) s[threadIdx.x] = fmaxf(s[threadIdx.x], s[threadIdx.x + o]);
        __syncthreads();
    }
    if (threadIdx.x == 0) atomicMax(&g_maxbits, __float_as_uint(s[0]));
}

__global__ void k_bn(const float* __restrict__ gamma, const float* __restrict__ beta,
                     const float* __restrict__ mean, const float* __restrict__ var) {
    int i = threadIdx.x;
    if (i < COUT) {
        float inv = gamma[i] / sqrtf(var[i] + 1e-5f);
        g_scale[i] = inv * (1.f / 15.f);
        g_bias[i]  = beta[i] - mean[i] * inv;
    }
}

// weights -> integer m = 2k-15 (exact in bf16), pre-swizzled 16KB A tiles
__global__ void k_prepw(const float* __restrict__ w) {
    int idx = blockIdx.x * blockDim.x + threadIdx.x;
    if (idx >= COUT * CIN * 9) return;
    float T = tanhf(__uint_as_float(g_maxbits));
    int oc  = idx / (CIN * 9);
    int rem = idx - oc * (CIN * 9);
    int ic  = rem / 9;
    int tap = rem - ic * 9;
    float t = tanhf(w[idx]);
    float k = rintf((t / (2.f * T) + 0.5f) * 15.f);   // 0..15
    float m = 2.f * k - 15.f;                          // odd int, |m|<=15
    int chunk = ic >> 6, icc = ic & 63;
    int mh = oc >> 7, row = oc & 127;
    int tile = (tap * 4 + chunk) * 2 + mh;
    int byte = row * 128 + icc * 2;
    int sw = byte ^ ((byte >> 3) & 0x70);
    g_A[tile * 8192 + (sw >> 1)] = __float2bfloat16(m);
}

// NCHW fp32 -> NHWC bf16 hi + lo
__global__ void k_prepx(const float* __restrict__ x) {
    __shared__ float s[64][57];
    int y = blockIdx.x, b = blockIdx.y;
    int tid = threadIdx.x;
    for (int ch = 0; ch < 4; ++ch) {
        for (int i = tid; i < 64 * 56; i += 256) {
            int ic = i / 56, xx = i - ic * 56;
            s[ic][xx] = x[(((size_t)b * CIN + ch * 64 + ic) * H_ + y) * W_ + xx];
        }
        __syncthreads();
        for (int i = tid; i < 56 * 64; i += 256) {
            int xx = i >> 6, ic = i & 63;
            float v = s[ic][xx];
            __nv_bfloat16 hi = __float2bfloat16(v);
            __nv_bfloat16 lo = __float2bfloat16(v - __bfloat162float(hi));
            size_t dst = (((size_t)b * H_ + y) * W_ + xx) * CIN + ch * 64 + ic;
            g_xhi[dst] = hi;
            g_xlo[dst] = lo;
        }
        __syncthreads();
    }
}

// ---------- conv: HMMA implicit GEMM (R5 shape + frag double-buffer) ----------
// smem: A0 @0, A1 @16K, B0 @32K, B1 @48K  (all 128 rows x 128B, swizzled)
#define SA0 0
#define SA1 16384
#define SB0 32768
#define SB1 49152
#define SM_TOT 65536

__global__ __launch_bounds__(256, 2)
void k_conv(const float* __restrict__ alpha, float* __restrict__ out) {
    extern __shared__ char smem[];
    const uint32_t sb = smem_u32(smem);
    const int tid = threadIdx.x, wid = tid >> 5, lane = tid & 31;
    const int tile = blockIdx.x;           // n tile (0..24)
    const int mh   = blockIdx.y;           // 0..1
    const int b    = blockIdx.z;
    const int wm = wid >> 2;               // 0..1 -> m offset 64*wm
    const int wn = wid & 3;                // 0..3 -> n offset 32*wn

    const uint32_t aoff[2] = {SA0, SA1};
    const uint32_t boff[2] = {SB0, SB1};

    int rowi[4], qi[4];
    uint32_t dsw[4];
    #pragma unroll
    for (int j = 0; j < 4; ++j) {
        int idx = tid + j * 256;
        rowi[j] = idx >> 3; qi[j] = idx & 7;
        dsw[j] = rowi[j] * 128 + ((qi[j] ^ (rowi[j] & 7)) * 16);
    }

    auto prefetch = [&](int s) {
        const int pair = s >> 1, split = s & 1;
        const int tap = pair >> 2, chunk = pair & 3;
        if (split == 0) {  // stage A: linear copy of pre-swizzled tile, L1-bypass
            const char* Asrc = (const char*)g_A + (size_t)((tap * 4 + chunk) * 2 + mh) * 16384;
            uint32_t Ad = sb + aoff[pair & 1];
            #pragma unroll
            for (int j = 0; j < 4; ++j) {
                int idx = tid + j * 256;
                cp16cg(Ad + idx * 16, Asrc + idx * 16);
            }
        }
        {   // stage B: 128 px rows x 128B, swizzle on store, zfill OOB/halo
            const __nv_bfloat16* xs = split ? g_xlo : g_xhi;
            const int dy = tap / 3 - 1, dx = tap % 3 - 1;
            uint32_t Bd = sb + boff[s & 1];
            #pragma unroll
            for (int j = 0; j < 4; ++j) {
                int px = tile * NTILE + rowi[j];
                int y = px / 56, xx = px - y * 56;
                int gy = y + dy, gx = xx + dx;
                bool ok = (px < PX) && ((unsigned)gy < (unsigned)H_) && ((unsigned)gx < (unsigned)W_);
                const __nv_bfloat16* src = ok
                    ? xs + ((((size_t)b * H_ + gy) * W_ + gx) * CIN + chunk * 64 + qi[j] * 8)
                    : xs;
                cp16ca(Bd + dsw[j], src, ok ? 16u : 0u);
            }
        }
        CP_COMMIT();
    };

    float acc[4][4][4];
    #pragma unroll
    for (int i = 0; i < 4; ++i)
        #pragma unroll
        for (int jj = 0; jj < 4; ++jj)
            #pragma unroll
            for (int kq = 0; kq < 4; ++kq) acc[i][jj][kq] = 0.f;

    prefetch(0);

    const int lrow = lane & 15;
    const int lkh  = lane >> 4;

    // fragment double buffers
    uint32_t aF[2][4][4], bF[2][2][4];

    for (int s = 0; s < 72; ++s) {
        if (s + 1 < 72) { prefetch(s + 1); CP_WAIT(1); }
        else            { CP_WAIT(0); }
        __syncthreads();

        const uint32_t Ab = sb + aoff[(s >> 1) & 1];
        const uint32_t Bb = sb + boff[s & 1];

        // load k-step 0 fragments into buffer 0
        {
            const int qbase = lkh;
            #pragma unroll
            for (int mt = 0; mt < 4; ++mt) {
                int r = wm * 64 + mt * 16 + lrow;
                ldsm4(aF[0][mt][0], aF[0][mt][1], aF[0][mt][2], aF[0][mt][3],
                      Ab + r * 128 + ((qbase ^ (r & 7)) * 16));
            }
            #pragma unroll
            for (int bt = 0; bt < 2; ++bt) {
                int r = wn * 32 + bt * 16 + lrow;
                ldsm4(bF[0][bt][0], bF[0][bt][1], bF[0][bt][2], bF[0][bt][3],
                      Bb + r * 128 + ((qbase ^ (r & 7)) * 16));
            }
        }

        #pragma unroll
        for (int ks = 0; ks < 4; ++ks) {
            const int cur = ks & 1, nxt = cur ^ 1;
            if (ks < 3) {   // prefetch next k-step fragments BEFORE the MMAs
                const int qbase = (ks + 1) * 2 + lkh;
                #pragma unroll
                for (int mt = 0; mt < 4; ++mt) {
                    int r = wm * 64 + mt * 16 + lrow;
                    ldsm4(aF[nxt][mt][0], aF[nxt][mt][1], aF[nxt][mt][2], aF[nxt][mt][3],
                          Ab + r * 128 + ((qbase ^ (r & 7)) * 16));
                }
                #pragma unroll
                for (int bt = 0; bt < 2; ++bt) {
                    int r = wn * 32 + bt * 16 + lrow;
                    ldsm4(bF[nxt][bt][0], bF[nxt][bt][1], bF[nxt][bt][2], bF[nxt][bt][3],
                          Bb + r * 128 + ((qbase ^ (r & 7)) * 16));
                }
            }
            #pragma unroll
            for (int mt = 0; mt < 4; ++mt) {
                #pragma unroll
                for (int bt = 0; bt < 2; ++bt) {
                    mma16816(acc[mt][bt * 2 + 0], aF[cur][mt], bF[cur][bt][0], bF[cur][bt][2]);
                    mma16816(acc[mt][bt * 2 + 1], aF[cur][mt], bF[cur][bt][1], bF[cur][bt][3]);
                }
            }
        }
        __syncthreads();
    }

    // ---------- epilogue: BN + PACT, direct fp32 stores ----------
    const float av = alpha[0];
    const float istep = 15.f / av, step = av / 15.f;
    #pragma unroll
    for (int mt = 0; mt < 4; ++mt) {
        const int r0 = wm * 64 + mt * 16 + (lane >> 2);
        #pragma unroll
        for (int half = 0; half < 2; ++half) {
            const int oc = mh * 128 + r0 + half * 8;
            const float sc = g_scale[oc], bi = g_bias[oc];
            float* ob = out + ((size_t)b * COUT + oc) * PX;
            #pragma unroll
            for (int nt = 0; nt < 4; ++nt) {
                const int px = tile * NTILE + wn * 32 + nt * 8 + (lane & 3) * 2;
                if (px + 1 < PX) {
                    float y0 = acc[mt][nt][half * 2 + 0] * sc + bi;
                    float y1 = acc[mt][nt][half * 2 + 1] * sc + bi;
                    y0 = fminf(fmaxf(y0, 0.f), av);
                    y1 = fminf(fmaxf(y1, 0.f), av);
                    float2 v = make_float2(rintf(y0 * istep) * step, rintf(y1 * istep) * step);
                    *(float2*)(ob + px) = v;
                } else if (px < PX) {
                    float y0 = acc[mt][nt][half * 2 + 0] * sc + bi;
                    y0 = fminf(fmaxf(y0, 0.f), av);
                    ob[px] = rintf(y0 * istep) * step;
                }
            }
        }
    }
}

extern "C" void kernel_launch(void* const* d_in, const int* in_sizes, int n_in,
                              void* d_out, int out_size) {
    const float* x      = (const float*)d_in[0];
    const float* weight = (const float*)d_in[1];
    const float* gamma  = (const float*)d_in[2];
    const float* beta   = (const float*)d_in[3];
    const float* mean   = (const float*)d_in[4];
    const float* var    = (const float*)d_in[5];
    const float* alpha  = (const float*)d_in[6];
    float* out = (float*)d_out;

    k_init<<<1, 32>>>();
    k_bn<<<1, 256>>>(gamma, beta, mean, var);
    k_maxred<<<576, 256>>>(weight, COUT * CIN * 9);
    k_prepw<<<(COUT * CIN * 9 + 255) / 256, 256>>>(weight);
    k_prepx<<<dim3(H_, B_), 256>>>(x);

    cudaFuncSetAttribute(k_conv, cudaFuncAttributeMaxDynamicSharedMemorySize, SM_TOT);
    k_conv<<<dim3(NTILES, 2, B_), 256, SM_TOT>>>(alpha, out);
    (void)in_sizes; (void)n_in; (void)out_size;
}

// round 13
// speedup vs baseline: 1.0912x; 1.0220x over previous
#include <cuda_runtime.h>
#include <cuda_bf16.h>
#include <cstdint>

#define B_   32
#define CIN  256
#define COUT 256
#define H_   56
#define W_   56
#define PX   (H_ * W_)        // 3136
#define NTILE 128             // px per CTA
#define NTILES 25             // ceil(3136/128)

// ---------- static scratch ----------
__device__ __align__(16) __nv_bfloat16 g_xhi[(size_t)B_ * PX * CIN];  // NHWC hi
__device__ __align__(16) __nv_bfloat16 g_xlo[(size_t)B_ * PX * CIN];  // NHWC lo
// A tiles: [tap][chunk][mhalf][row 0..127][64 ic] bf16, rows 128B, pre-swizzled, 16KB each
__device__ __align__(16) __nv_bfloat16 g_A[9 * 4 * 2 * 128 * 64];
__device__ float g_scale[COUT];   // inv/15
__device__ float g_bias[COUT];
__device__ unsigned g_maxbits;

// ---------- helpers ----------
__device__ __forceinline__ uint32_t smem_u32(const void* p) {
    uint32_t a;
    asm("{ .reg .u64 t; cvta.to.shared.u64 t, %1; cvt.u32.u64 %0, t; }" : "=r"(a) : "l"(p));
    return a;
}
__device__ __forceinline__ void cp16ca(uint32_t s, const void* g, uint32_t bytes) {
    asm volatile("cp.async.ca.shared.global [%0], [%1], 16, %2;"
                 :: "r"(s), "l"(g), "r"(bytes) : "memory");
}
__device__ __forceinline__ void cp16cg(uint32_t s, const void* g) {
    asm volatile("cp.async.cg.shared.global [%0], [%1], 16;"
                 :: "r"(s), "l"(g) : "memory");
}
#define CP_COMMIT() asm volatile("cp.async.commit_group;" ::: "memory")
#define CP_WAIT(n)  asm volatile("cp.async.wait_group %0;" :: "n"(n) : "memory")

__device__ __forceinline__ void ldsm4(uint32_t& r0, uint32_t& r1, uint32_t& r2, uint32_t& r3, uint32_t a) {
    asm volatile("ldmatrix.sync.aligned.m8n8.x4.shared.b16 {%0,%1,%2,%3}, [%4];"
                 : "=r"(r0), "=r"(r1), "=r"(r2), "=r"(r3) : "r"(a));
}
__device__ __forceinline__ void mma16816(float* c, const uint32_t* a, uint32_t b0, uint32_t b1) {
    asm volatile("mma.sync.aligned.m16n8k16.row.col.f32.bf16.bf16.f32 "
                 "{%0,%1,%2,%3}, {%4,%5,%6,%7}, {%8,%9}, {%0,%1,%2,%3};"
                 : "+f"(c[0]), "+f"(c[1]), "+f"(c[2]), "+f"(c[3])
                 : "r"(a[0]), "r"(a[1]), "r"(a[2]), "r"(a[3]), "r"(b0), "r"(b1));
}

// ---------- prep kernels ----------
__global__ void k_init() { if (threadIdx.x == 0) g_maxbits = 0u; }

__global__ void k_maxred(const float* __restrict__ w, int n) {
    __shared__ float s[256];
    float m = 0.f;
    for (int i = blockIdx.x * blockDim.x + threadIdx.x; i < n; i += gridDim.x * blockDim.x)
        m = fmaxf(m, fabsf(w[i]));
    s[threadIdx.x] = m;
    __syncthreads();
    for (int o = 128; o > 0; o >>= 1) {
        if (threadIdx.x < o) s[threadIdx.x] = fmaxf(s[threadIdx.x], s[threadIdx.x + o]);
        __syncthreads();
    }
    if (threadIdx.x == 0) atomicMax(&g_maxbits, __float_as_uint(s[0]));
}

__global__ void k_bn(const float* __restrict__ gamma, const float* __restrict__ beta,
                     const float* __restrict__ mean, const float* __restrict__ var) {
    int i = threadIdx.x;
    if (i < COUT) {
        float inv = gamma[i] / sqrtf(var[i] + 1e-5f);
        g_scale[i] = inv * (1.f / 15.f);
        g_bias[i]  = beta[i] - mean[i] * inv;
    }
}

// weights -> integer m = 2k-15 (exact in bf16), pre-swizzled 16KB A tiles
__global__ void k_prepw(const float* __restrict__ w) {
    int idx = blockIdx.x * blockDim.x + threadIdx.x;
    if (idx >= COUT * CIN * 9) return;
    float T = tanhf(__uint_as_float(g_maxbits));
    int oc  = idx / (CIN * 9);
    int rem = idx - oc * (CIN * 9);
    int ic  = rem / 9;
    int tap = rem - ic * 9;
    float t = tanhf(w[idx]);
    float k = rintf((t / (2.f * T) + 0.5f) * 15.f);   // 0..15
    float m = 2.f * k - 15.f;                          // odd int, |m|<=15
    int chunk = ic >> 6, icc = ic & 63;
    int mh = oc >> 7, row = oc & 127;
    int tile = (tap * 4 + chunk) * 2 + mh;
    int byte = row * 128 + icc * 2;
    int sw = byte ^ ((byte >> 3) & 0x70);
    g_A[tile * 8192 + (sw >> 1)] = __float2bfloat16(m);
}

// NCHW fp32 -> NHWC bf16 hi + lo
__global__ void k_prepx(const float* __restrict__ x) {
    __shared__ float s[64][57];
    int y = blockIdx.x, b = blockIdx.y;
    int tid = threadIdx.x;
    for (int ch = 0; ch < 4; ++ch) {
        for (int i = tid; i < 64 * 56; i += 256) {
            int ic = i / 56, xx = i - ic * 56;
            s[ic][xx] = x[(((size_t)b * CIN + ch * 64 + ic) * H_ + y) * W_ + xx];
        }
        __syncthreads();
        for (int i = tid; i < 56 * 64; i += 256) {
            int xx = i >> 6, ic = i & 63;
            float v = s[ic][xx];
            __nv_bfloat16 hi = __float2bfloat16(v);
            __nv_bfloat16 lo = __float2bfloat16(v - __bfloat162float(hi));
            size_t dst = (((size_t)b * H_ + y) * W_ + xx) * CIN + ch * 64 + ic;
            g_xhi[dst] = hi;
            g_xlo[dst] = lo;
        }
        __syncthreads();
    }
}

// ---------- conv: HMMA implicit GEMM, 4 warps x (64x64) tiles ----------
// smem: A0 @0, A1 @16K, B0 @32K, B1 @48K  (all 128 rows x 128B, swizzled)
#define SA0 0
#define SA1 16384
#define SB0 32768
#define SB1 49152
#define SM_TOT 65536

__global__ __launch_bounds__(128, 2)
void k_conv(const float* __restrict__ alpha, float* __restrict__ out) {
    extern __shared__ char smem[];
    const uint32_t sb = smem_u32(smem);
    const int tid = threadIdx.x, wid = tid >> 5, lane = tid & 31;
    const int tile = blockIdx.x;           // n tile (0..24)
    const int mh   = blockIdx.y;           // 0..1
    const int b    = blockIdx.z;
    const int wm = wid >> 1;               // 0..1 -> m offset 64*wm
    const int wn = wid & 1;                // 0..1 -> n offset 64*wn

    const uint32_t aoff[2] = {SA0, SA1};
    const uint32_t boff[2] = {SB0, SB1};

    // per-thread prefetch slices: 1024 chunks of 16B, 8 per thread (128 threads)
    int rowi[8], qi[8];
    uint32_t dsw[8];
    #pragma unroll
    for (int j = 0; j < 8; ++j) {
        int idx = tid + j * 128;
        rowi[j] = idx >> 3; qi[j] = idx & 7;
        dsw[j] = rowi[j] * 128 + ((qi[j] ^ (rowi[j] & 7)) * 16);
    }

    auto prefetch = [&](int s) {
        const int pair = s >> 1, split = s & 1;
        const int tap = pair >> 2, chunk = pair & 3;
        if (split == 0) {  // stage A: linear copy of pre-swizzled tile, L1-bypass
            const char* Asrc = (const char*)g_A + (size_t)((tap * 4 + chunk) * 2 + mh) * 16384;
            uint32_t Ad = sb + aoff[pair & 1];
            #pragma unroll
            for (int j = 0; j < 8; ++j) {
                int idx = tid + j * 128;
                cp16cg(Ad + idx * 16, Asrc + idx * 16);
            }
        }
        {   // stage B: 128 px rows x 128B, swizzle on store, zfill OOB/halo
            const __nv_bfloat16* xs = split ? g_xlo : g_xhi;
            const int dy = tap / 3 - 1, dx = tap % 3 - 1;
            uint32_t Bd = sb + boff[s & 1];
            #pragma unroll
            for (int j = 0; j < 8; ++j) {
                int px = tile * NTILE + rowi[j];
                int y = px / 56, xx = px - y * 56;
                int gy = y + dy, gx = xx + dx;
                bool ok = (px < PX) && ((unsigned)gy < (unsigned)H_) && ((unsigned)gx < (unsigned)W_);
                const __nv_bfloat16* src = ok
                    ? xs + ((((size_t)b * H_ + gy) * W_ + gx) * CIN + chunk * 64 + qi[j] * 8)
                    : xs;
                cp16ca(Bd + dsw[j], src, ok ? 16u : 0u);
            }
        }
        CP_COMMIT();
    };

    float acc[4][8][4];
    #pragma unroll
    for (int i = 0; i < 4; ++i)
        #pragma unroll
        for (int jj = 0; jj < 8; ++jj)
            #pragma unroll
            for (int kq = 0; kq < 4; ++kq) acc[i][jj][kq] = 0.f;

    prefetch(0);

    const int lrow = lane & 15;
    const int lkh  = lane >> 4;

    for (int s = 0; s < 72; ++s) {
        if (s + 1 < 72) { prefetch(s + 1); CP_WAIT(1); }
        else            { CP_WAIT(0); }
        __syncthreads();

        const uint32_t Ab = sb + aoff[(s >> 1) & 1];
        const uint32_t Bb = sb + boff[s & 1];

        #pragma unroll
        for (int ks = 0; ks < 4; ++ks) {
            const int qbase = ks * 2 + lkh;
            uint32_t a[4][4];
            #pragma unroll
            for (int mt = 0; mt < 4; ++mt) {
                int r = wm * 64 + mt * 16 + lrow;
                ldsm4(a[mt][0], a[mt][1], a[mt][2], a[mt][3],
                      Ab + r * 128 + ((qbase ^ (r & 7)) * 16));
            }
            uint32_t br[4][4];
            #pragma unroll
            for (int bt = 0; bt < 4; ++bt) {
                int r = wn * 64 + bt * 16 + lrow;
                ldsm4(br[bt][0], br[bt][1], br[bt][2], br[bt][3],
                      Bb + r * 128 + ((qbase ^ (r & 7)) * 16));
            }
            #pragma unroll
            for (int mt = 0; mt < 4; ++mt) {
                #pragma unroll
                for (int bt = 0; bt < 4; ++bt) {
                    mma16816(acc[mt][bt * 2 + 0], a[mt], br[bt][0], br[bt][2]);
                    mma16816(acc[mt][bt * 2 + 1], a[mt], br[bt][1], br[bt][3]);
                }
            }
        }
        __syncthreads();
    }

    // ---------- epilogue: BN + PACT, direct fp32 stores ----------
    const float av = alpha[0];
    const float istep = 15.f / av, step = av / 15.f;
    #pragma unroll
    for (int mt = 0; mt < 4; ++mt) {
        const int r0 = wm * 64 + mt * 16 + (lane >> 2);
        #pragma unroll
        for (int half = 0; half < 2; ++half) {
            const int oc = mh * 128 + r0 + half * 8;
            const float sc = g_scale[oc], bi = g_bias[oc];
            float* ob = out + ((size_t)b * COUT + oc) * PX;
            #pragma unroll
            for (int nt = 0; nt < 8; ++nt) {
                const int px = tile * NTILE + wn * 64 + nt * 8 + (lane & 3) * 2;
                if (px + 1 < PX) {
                    float y0 = acc[mt][nt][half * 2 + 0] * sc + bi;
                    float y1 = acc[mt][nt][half * 2 + 1] * sc + bi;
                    y0 = fminf(fmaxf(y0, 0.f), av);
                    y1 = fminf(fmaxf(y1, 0.f), av);
                    float2 v = make_float2(rintf(y0 * istep) * step, rintf(y1 * istep) * step);
                    *(float2*)(ob + px) = v;
                } else if (px < PX) {
                    float y0 = acc[mt][nt][half * 2 + 0] * sc + bi;
                    y0 = fminf(fmaxf(y0, 0.f), av);
                    ob[px] = rintf(y0 * istep) * step;
                }
            }
        }
    }
}

extern "C" void kernel_launch(void* const* d_in, const int* in_sizes, int n_in,
                              void* d_out, int out_size) {
    const float* x      = (const float*)d_in[0];
    const float* weight = (const float*)d_in[1];
    const float* gamma  = (const float*)d_in[2];
    const float* beta   = (const float*)d_in[3];
    const float* mean   = (const float*)d_in[4];
    const float* var    = (const float*)d_in[5];
    const float* alpha  = (const float*)d_in[6];
    float* out = (float*)d_out;

    k_init<<<1, 32>>>();
    k_bn<<<1, 256>>>(gamma, beta, mean, var);
    k_maxred<<<576, 256>>>(weight, COUT * CIN * 9);
    k_prepw<<<(COUT * CIN * 9 + 255) / 256, 256>>>(weight);
    k_prepx<<<dim3(H_, B_), 256>>>(x);

    cudaFuncSetAttribute(k_conv, cudaFuncAttributeMaxDynamicSharedMemorySize, SM_TOT);
    k_conv<<<dim3(NTILES, 2, B_), 128, SM_TOT>>>(alpha, out);
    (void)in_sizes; (void)n_in; (void)out_size;
}